// round 2
// baseline (speedup 1.0000x reference)
#include <cuda_runtime.h>

#define WDIM 512
#define HDIM 512
#define HW   262144      // 512*512
#define NB   8
#define NPIX (NB * HW)   // 2,097,152

__device__ double g_acc;

__global__ void zero_acc_kernel() { g_acc = 0.0; }

__device__ __forceinline__ float clipf(float v) {
    return fminf(fmaxf(v, 1e-10f), 1.0f - 1e-10f);
}

__global__ void __launch_bounds__(256) flow_loss_kernel(
    const float* __restrict__ roi_mask,
    const float* __restrict__ hm_0,
    const float* __restrict__ hm_1,
    const float* __restrict__ hm_2,
    const float* __restrict__ rec_1pf,
    const float* __restrict__ rec_1pb,
    const float* __restrict__ rec_1nf,
    const float* __restrict__ rec_1nb,
    const float* __restrict__ rec_0f,
    const float* __restrict__ rec_0b,
    const float* __restrict__ rec_2f,
    const float* __restrict__ rec_2b,
    const float* __restrict__ f01f,
    const float* __restrict__ f10b,
    const float* __restrict__ f12f,
    const float* __restrict__ f21b)
{
    const int idx = blockIdx.x * blockDim.x + threadIdx.x;
    float acc = 0.0f;

    if (idx < NPIX) {
        const int x = idx & (WDIM - 1);
        const int y = (idx >> 9) & (HDIM - 1);
        const int b = idx >> 18;

        const float roi = roi_mask[idx];

        // ---------- heatmap reconstruction losses ----------
        const float h0 = hm_0[idx];
        const float h1 = hm_1[idx];
        const float h2 = hm_2[idx];
        const float wpre  = 1.0f + fabsf(h0 - h1);   // 1 + RF*pre, RF=1
        const float wpost = 1.0f + fabsf(h1 - h2);

        float d;
        float s1 = 0.0f;
        d = rec_1pf[idx] - h1; s1 += d * d * wpre;
        d = rec_1pb[idx] - h1; s1 += d * d * wpre;
        d = rec_1nf[idx] - h1; s1 += d * d * wpost;
        d = rec_1nb[idx] - h1; s1 += d * d * wpost;

        float s0 = 0.0f;
        d = rec_0f[idx] - h0; s0 += d * d;
        d = rec_0b[idx] - h0; s0 += d * d;

        float s2 = 0.0f;
        d = rec_2f[idx] - h2; s2 += d * d;
        d = rec_2b[idx] - h2; s2 += d * d;

        acc = roi * (0.25f * s1 + 0.5f * (s0 * wpre) + 0.5f * (s2 * wpost));

        // ---------- flow consistency (both pairs, all 9 channels) ----------
        // a = flow[b, i, y, x]  pairs with  b = flow_inv[b, 8-i, y-dy, x-dx]
        // valid iff (y-dy) in [0,H) and (x-dx) in [0,W); mask = roi[b, y, x]
        const int base9 = b * 9 * HW;
        const int pix   = (y << 9) + x;

        float fsum = 0.0f;
        #pragma unroll
        for (int i = 0; i < 9; ++i) {
            const int dy = (i < 3) ? 1 : ((i < 6) ? 0 : -1);
            const int m  = i % 3;
            const int dx = (m == 0) ? 1 : ((m == 1) ? 0 : -1);
            const int yy = y - dy;
            const int xx = x - dx;
            if ((unsigned)yy < (unsigned)HDIM && (unsigned)xx < (unsigned)WDIM) {
                const int ai = base9 + i * HW + pix;
                const int bi = base9 + (8 - i) * HW + (yy << 9) + xx;

                const float a1 = clipf(f01f[ai]);
                const float b1 = clipf(f10b[bi]);
                const float d1 = a1 - b1;

                const float a2 = clipf(f12f[ai]);
                const float b2 = clipf(f21b[bi]);
                const float d2 = a2 - b2;

                fsum += d1 * d1 + d2 * d2;
            }
        }
        acc += roi * fsum * (1.0f / 9.0f);
    }

    // ---------- reduction: warp -> block -> global atomic (double) ----------
    double v = (double)acc;
    #pragma unroll
    for (int off = 16; off > 0; off >>= 1)
        v += __shfl_down_sync(0xffffffffu, v, off);

    __shared__ double sdata[8];
    const int lane = threadIdx.x & 31;
    const int warp = threadIdx.x >> 5;
    if (lane == 0) sdata[warp] = v;
    __syncthreads();

    if (warp == 0) {
        v = (lane < 8) ? sdata[lane] : 0.0;
        #pragma unroll
        for (int off = 4; off > 0; off >>= 1)
            v += __shfl_down_sync(0x000000ffu, v, off);
        if (lane == 0) atomicAdd(&g_acc, v);
    }
}

__global__ void finalize_kernel(float* __restrict__ out) {
    out[0] = (float)g_acc;
}

extern "C" void kernel_launch(void* const* d_in, const int* in_sizes, int n_in,
                              void* d_out, int out_size) {
    // metadata order: roi_mask, boundary_mask, hm_0, hm_1, hm_2,
    //                 rec_1pf, rec_1pb, rec_1nf, rec_1nb,
    //                 rec_0f, rec_0b, rec_2f, rec_2b,
    //                 flow_0_1f, flow_1_0b, flow_1_2f, flow_2_1b
    const float* roi_mask = (const float*)d_in[0];
    // d_in[1] boundary_mask: unused by the reference
    const float* hm_0     = (const float*)d_in[2];
    const float* hm_1     = (const float*)d_in[3];
    const float* hm_2     = (const float*)d_in[4];
    const float* rec_1pf  = (const float*)d_in[5];
    const float* rec_1pb  = (const float*)d_in[6];
    const float* rec_1nf  = (const float*)d_in[7];
    const float* rec_1nb  = (const float*)d_in[8];
    const float* rec_0f   = (const float*)d_in[9];
    const float* rec_0b   = (const float*)d_in[10];
    const float* rec_2f   = (const float*)d_in[11];
    const float* rec_2b   = (const float*)d_in[12];
    const float* f01f     = (const float*)d_in[13];
    const float* f10b     = (const float*)d_in[14];
    const float* f12f     = (const float*)d_in[15];
    const float* f21b     = (const float*)d_in[16];

    zero_acc_kernel<<<1, 1>>>();

    const int threads = 256;
    const int blocks  = NPIX / threads;  // 8192
    flow_loss_kernel<<<blocks, threads>>>(
        roi_mask, hm_0, hm_1, hm_2,
        rec_1pf, rec_1pb, rec_1nf, rec_1nb,
        rec_0f, rec_0b, rec_2f, rec_2b,
        f01f, f10b, f12f, f21b);

    finalize_kernel<<<1, 1>>>((float*)d_out);
}

// round 3
// speedup vs baseline: 1.1764x; 1.1764x over previous
#include <cuda_runtime.h>

#define WDIM 512
#define HDIM 512
#define HW   262144      // 512*512
#define NB   8
#define NPIX (NB * HW)   // 2,097,152
#define QUADS (NPIX / 4) // 524,288

__device__ double g_acc = 0.0;   // invariant: 0 at kernel_launch entry

__device__ __forceinline__ float clipf(float v) {
    return fminf(fmaxf(v, 1e-10f), 1.0f - 1e-10f);
}

__device__ __forceinline__ float4 ldg4(const float* p) {
    return __ldg(reinterpret_cast<const float4*>(p));
}

__device__ __forceinline__ float comp(const float4& v, int k) {
    return (k == 0) ? v.x : (k == 1) ? v.y : (k == 2) ? v.z : v.w;
}

__global__ void __launch_bounds__(256) flow_loss_kernel(
    const float* __restrict__ roi_mask,
    const float* __restrict__ hm_0,
    const float* __restrict__ hm_1,
    const float* __restrict__ hm_2,
    const float* __restrict__ rec_1pf,
    const float* __restrict__ rec_1pb,
    const float* __restrict__ rec_1nf,
    const float* __restrict__ rec_1nb,
    const float* __restrict__ rec_0f,
    const float* __restrict__ rec_0b,
    const float* __restrict__ rec_2f,
    const float* __restrict__ rec_2b,
    const float* __restrict__ f01f,
    const float* __restrict__ f10b,
    const float* __restrict__ f12f,
    const float* __restrict__ f21b)
{
    const int q = blockIdx.x * blockDim.x + threadIdx.x;   // quad index
    float acc = 0.0f;

    if (q < QUADS) {
        const int p   = q << 2;                 // base pixel index
        const int x0  = p & (WDIM - 1);         // multiple of 4
        const int y   = (p >> 9) & (HDIM - 1);
        const int b   = p >> 18;

        const float4 roi = ldg4(roi_mask + p);

        // ---------- heatmap reconstruction losses (vectorized streams) ----
        const float4 h0  = ldg4(hm_0 + p);
        const float4 h1  = ldg4(hm_1 + p);
        const float4 h2  = ldg4(hm_2 + p);
        const float4 r1a = ldg4(rec_1pf + p);
        const float4 r1b = ldg4(rec_1pb + p);
        const float4 r1c = ldg4(rec_1nf + p);
        const float4 r1d = ldg4(rec_1nb + p);
        const float4 r0a = ldg4(rec_0f + p);
        const float4 r0b = ldg4(rec_0b + p);
        const float4 r2a = ldg4(rec_2f + p);
        const float4 r2b = ldg4(rec_2b + p);

        float hmk[4];
        #pragma unroll
        for (int k = 0; k < 4; ++k) {
            const float H0 = comp(h0, k), H1 = comp(h1, k), H2 = comp(h2, k);
            const float wpre  = 1.0f + fabsf(H0 - H1);
            const float wpost = 1.0f + fabsf(H1 - H2);
            float d, s1 = 0.0f;
            d = comp(r1a, k) - H1; s1 += d * d * wpre;
            d = comp(r1b, k) - H1; s1 += d * d * wpre;
            d = comp(r1c, k) - H1; s1 += d * d * wpost;
            d = comp(r1d, k) - H1; s1 += d * d * wpost;
            float s0 = 0.0f;
            d = comp(r0a, k) - H0; s0 += d * d;
            d = comp(r0b, k) - H0; s0 += d * d;
            float s2 = 0.0f;
            d = comp(r2a, k) - H2; s2 += d * d;
            d = comp(r2b, k) - H2; s2 += d * d;
            hmk[k] = 0.25f * s1 + 0.5f * s0 * wpre + 0.5f * s2 * wpost;
        }

        // ---------- flow consistency ----------
        // flow[b,i,y,x]  pairs with  flow_inv[b,8-i,y-dy,x-dx]
        const int base9 = b * 9 * HW;
        const int rowp  = base9 + (y << 9) + x0;

        float fsum[4] = {0.0f, 0.0f, 0.0f, 0.0f};

        #pragma unroll
        for (int i = 0; i < 9; ++i) {
            const int dy = (i < 3) ? 1 : ((i < 6) ? 0 : -1);
            const int m  = i % 3;
            const int dx = (m == 0) ? 1 : ((m == 1) ? 0 : -1);
            const int yy = y - dy;
            if ((unsigned)yy >= (unsigned)HDIM) continue;   // uniform per thread

            const float4 a1 = ldg4(f01f + rowp + i * HW);
            const float4 a2 = ldg4(f12f + rowp + i * HW);

            const int invrow = base9 + (8 - i) * HW + (yy << 9);

            if (dx == 0) {
                const float4 b1 = ldg4(f10b + invrow + x0);
                const float4 b2 = ldg4(f21b + invrow + x0);
                #pragma unroll
                for (int k = 0; k < 4; ++k) {
                    const float d1 = clipf(comp(a1, k)) - clipf(comp(b1, k));
                    const float d2 = clipf(comp(a2, k)) - clipf(comp(b2, k));
                    fsum[k] += d1 * d1 + d2 * d2;
                }
            } else {
                #pragma unroll
                for (int k = 0; k < 4; ++k) {
                    const int xx = x0 + k - dx;
                    if ((unsigned)xx < (unsigned)WDIM) {
                        const float b1 = __ldg(f10b + invrow + xx);
                        const float b2 = __ldg(f21b + invrow + xx);
                        const float d1 = clipf(comp(a1, k)) - clipf(b1);
                        const float d2 = clipf(comp(a2, k)) - clipf(b2);
                        fsum[k] += d1 * d1 + d2 * d2;
                    }
                }
            }
        }

        #pragma unroll
        for (int k = 0; k < 4; ++k)
            acc += comp(roi, k) * (hmk[k] + fsum[k] * (1.0f / 9.0f));
    }

    // ---------- reduction: warp -> block -> global atomic (double) --------
    double v = (double)acc;
    #pragma unroll
    for (int off = 16; off > 0; off >>= 1)
        v += __shfl_down_sync(0xffffffffu, v, off);

    __shared__ double sdata[8];
    const int lane = threadIdx.x & 31;
    const int warp = threadIdx.x >> 5;
    if (lane == 0) sdata[warp] = v;
    __syncthreads();

    if (warp == 0) {
        v = (lane < 8) ? sdata[lane] : 0.0;
        #pragma unroll
        for (int off = 4; off > 0; off >>= 1)
            v += __shfl_down_sync(0x000000ffu, v, off);
        if (lane == 0) atomicAdd(&g_acc, v);
    }
}

__global__ void finalize_kernel(float* __restrict__ out) {
    out[0] = (float)g_acc;
    g_acc = 0.0;   // restore invariant for the next launch / graph replay
}

extern "C" void kernel_launch(void* const* d_in, const int* in_sizes, int n_in,
                              void* d_out, int out_size) {
    const float* roi_mask = (const float*)d_in[0];
    // d_in[1] boundary_mask: unused by the reference
    const float* hm_0     = (const float*)d_in[2];
    const float* hm_1     = (const float*)d_in[3];
    const float* hm_2     = (const float*)d_in[4];
    const float* rec_1pf  = (const float*)d_in[5];
    const float* rec_1pb  = (const float*)d_in[6];
    const float* rec_1nf  = (const float*)d_in[7];
    const float* rec_1nb  = (const float*)d_in[8];
    const float* rec_0f   = (const float*)d_in[9];
    const float* rec_0b   = (const float*)d_in[10];
    const float* rec_2f   = (const float*)d_in[11];
    const float* rec_2b   = (const float*)d_in[12];
    const float* f01f     = (const float*)d_in[13];
    const float* f10b     = (const float*)d_in[14];
    const float* f12f     = (const float*)d_in[15];
    const float* f21b     = (const float*)d_in[16];

    const int threads = 256;
    const int blocks  = QUADS / threads;   // 2048
    flow_loss_kernel<<<blocks, threads>>>(
        roi_mask, hm_0, hm_1, hm_2,
        rec_1pf, rec_1pb, rec_1nf, rec_1nb,
        rec_0f, rec_0b, rec_2f, rec_2b,
        f01f, f10b, f12f, f21b);

    finalize_kernel<<<1, 1>>>((float*)d_out);
}